// round 13
// baseline (speedup 1.0000x reference)
#include <cuda_runtime.h>
#include <cuda_bf16.h>
#include <cstdint>

// Problem constants
#define N_NODES 50000
#define E_EDGES 300000
#define IN_F    128
#define HFEAT   64
#define AHEADS  4
#define R_REL   3
#define H_DIM   256
#define RH      768          // R_REL * H_DIM
#define RN      (R_REL * N_NODES)
#define RE      (R_REL * E_EDGES)
#define NCHUNK  ((RN + 1023) / 1024)   // 147 scan chunks

// ---------------- device scratch (static, no allocations) ----------------
__device__ float g_hw [(size_t)N_NODES * RH];   // h @ [wW0|wW1|wW2] + bias (fp32)
__device__ float g_sa[N_NODES];
__device__ float g_sb[N_NODES];
__device__ float g_pq[(size_t)RN * 8];
__device__ float g_du[IN_F];
__device__ float g_dv[IN_F];
__device__ float g_PQ[R_REL * IN_F * 8];
__device__ float g_pqc[R_REL * 8];
__device__ float g_Cs;
__device__ int   g_cnt[RN];
__device__ int   g_off[RN + 1];
__device__ int   g_cur[RN];
__device__ int   g_elist[RE];          // stores SOURCE NODE ID of each edge (dst-CSR order)
__device__ int   g_pre[RN];
__device__ int   g_bsum[NCHUNK];
__device__ int   g_boff[NCHUNK];
// split-bf16 operands
__device__ __nv_bfloat16 g_hh[(size_t)N_NODES * IN_F];
__device__ __nv_bfloat16 g_hl[(size_t)N_NODES * IN_F];
__device__ __nv_bfloat16 g_aggh[(size_t)N_NODES * RH];
__device__ __nv_bfloat16 g_aggl[(size_t)N_NODES * RH];
// transposed+split weights
__device__ __nv_bfloat16 g_B1h[RH * IN_F];
__device__ __nv_bfloat16 g_B1l[RH * IN_F];
__device__ __nv_bfloat16 g_B2h[H_DIM * RH];
__device__ __nv_bfloat16 g_B2l[H_DIM * RH];

// ---------------- helpers ----------------
__device__ __forceinline__ void ldsm_x4(uint32_t& r0, uint32_t& r1, uint32_t& r2, uint32_t& r3,
                                        uint32_t addr)
{
    asm volatile("ldmatrix.sync.aligned.m8n8.x4.shared.b16 {%0,%1,%2,%3}, [%4];"
                 : "=r"(r0), "=r"(r1), "=r"(r2), "=r"(r3) : "r"(addr));
}
__device__ __forceinline__ void ldsm_x2(uint32_t& r0, uint32_t& r1, uint32_t addr)
{
    asm volatile("ldmatrix.sync.aligned.m8n8.x2.shared.b16 {%0,%1}, [%2];"
                 : "=r"(r0), "=r"(r1) : "r"(addr));
}
__device__ __forceinline__ void mma16816(float* d, const uint32_t* a, const uint32_t* b)
{
    asm volatile("mma.sync.aligned.m16n8k16.row.col.f32.bf16.bf16.f32 "
                 "{%0,%1,%2,%3}, {%4,%5,%6,%7}, {%8,%9}, {%0,%1,%2,%3};"
                 : "+f"(d[0]), "+f"(d[1]), "+f"(d[2]), "+f"(d[3])
                 : "r"(a[0]), "r"(a[1]), "r"(a[2]), "r"(a[3]), "r"(b[0]), "r"(b[1]));
}
__device__ __forceinline__ void split_bf16(float x, __nv_bfloat16& hi, __nv_bfloat16& lo)
{
    hi = __float2bfloat16_rn(x);
    lo = __float2bfloat16_rn(x - __bfloat162float(hi));
}
__device__ __forceinline__ uint32_t pack_bf2(__nv_bfloat16 a, __nv_bfloat16 b)
{
    return (uint32_t)__bfloat16_as_ushort(a) | ((uint32_t)__bfloat16_as_ushort(b) << 16);
}
__device__ __forceinline__ void cp_async16(uint32_t smem_addr, const void* gptr)
{
    asm volatile("cp.async.cg.shared.global [%0], [%1], 16;" :: "r"(smem_addr), "l"(gptr));
}
__device__ __forceinline__ void cp_commit()
{
    asm volatile("cp.async.commit_group;");
}
template <int N>
__device__ __forceinline__ void cp_wait()
{
    asm volatile("cp.async.wait_group %0;" :: "n"(N));
}
__device__ __forceinline__ float warp_sum(float v)
{
#pragma unroll
    for (int off = 16; off; off >>= 1) v += __shfl_xor_sync(0xffffffffu, v, off);
    return v;
}

// ---------------- tensor-core GEMM via mma.sync ----------------
// C[M,Ncols] = (Ah+Al)[M,K] @ (Bh+Bl)[Ncols,K]^T + bias (lo*lo dropped).
// Block tile 128x128, 8 warps of 64x32, K-chunk 64, 3 smem stages,
// register-level fragment double-buffering across ks-steps.
#define CK      64
#define SA_STR  72                      // bf16 per smem row (64 + 8 pad)
#define STG     (128 * SA_STR)          // elems per matrix per stage
#define MM_SMEM (3 * 4 * STG * 2)       // 221184 bytes
__global__ __launch_bounds__(256) void k_gemm_mma(const __nv_bfloat16* __restrict__ Ah,
                                                  const __nv_bfloat16* __restrict__ Al,
                                                  const __nv_bfloat16* __restrict__ Bh,
                                                  const __nv_bfloat16* __restrict__ Bl,
                                                  const float* __restrict__ bias,
                                                  float* __restrict__ C,
                                                  int M, int Ncols, int K)
{
    extern __shared__ __nv_bfloat16 smem[];
    uint32_t uBase = (uint32_t)__cvta_generic_to_shared(smem);

    int tid = threadIdx.x, wid = tid >> 5, lane = tid & 31;
    int m0 = blockIdx.y * 128, n0 = blockIdx.x * 128;
    int wm = (wid & 1) * 64, wn = (wid >> 1) * 32;

    float acc[4][4][4];
#pragma unroll
    for (int mt = 0; mt < 4; mt++)
#pragma unroll
        for (int nt = 0; nt < 4; nt++)
#pragma unroll
            for (int j = 0; j < 4; j++) acc[mt][nt][j] = 0.f;

    int lrow = tid >> 3, lch = tid & 7;
    int nch = K / CK;

    auto load_stage = [&](int st) {
        int kk = st * CK;
        uint32_t sb = uBase + (uint32_t)((st % 3) * 4 * STG * 2);
#pragma unroll
        for (int it = 0; it < 4; it++) {
            int row = lrow + it * 32;
            uint32_t so = (uint32_t)((row * SA_STR + lch * 8) * 2);
            int arow = m0 + row; if (arow >= M) arow = M - 1;
            size_t ga = (size_t)arow * K + kk + lch * 8;
            size_t gb = (size_t)(n0 + row) * K + kk + lch * 8;
            cp_async16(sb + 0 * STG * 2 + so, Ah + ga);
            cp_async16(sb + 1 * STG * 2 + so, Al + ga);
            cp_async16(sb + 2 * STG * 2 + so, Bh + gb);
            cp_async16(sb + 3 * STG * 2 + so, Bl + gb);
        }
        cp_commit();
    };

    load_stage(0);
    if (nch > 1) load_stage(1);

    // fragment addressing (fixed per thread)
    int brow = wn + (lane & 7);
    int bsel = ((lane >> 3) & 1) * 8;
    int arow_f = wm + (lane & 15);
    int asel = (lane >> 4) * 8;

    // double-buffered fragments
    uint32_t fbh[2][4][2], fbl[2][4][2], fah[2][4][4], fal[2][4][4];

    for (int c = 0; c < nch; c++) {
        if (c + 2 < nch) {
            load_stage(c + 2);
            cp_wait<2>();
        } else if (c + 1 < nch) {
            cp_wait<1>();
        } else {
            cp_wait<0>();
        }
        __syncthreads();

        uint32_t uAh = uBase + (uint32_t)((c % 3) * 4 * STG * 2);
        uint32_t uAl = uAh + STG * 2;
        uint32_t uBh = uAh + 2 * STG * 2;
        uint32_t uBl = uAh + 3 * STG * 2;

        // prologue: fragments for ks=0 into buf 0
#pragma unroll
        for (int nt = 0; nt < 4; nt++) {
            uint32_t ba = (uint32_t)(((brow + nt * 8) * SA_STR + bsel) * 2);
            ldsm_x2(fbh[0][nt][0], fbh[0][nt][1], uBh + ba);
            ldsm_x2(fbl[0][nt][0], fbl[0][nt][1], uBl + ba);
        }
#pragma unroll
        for (int mt = 0; mt < 4; mt++) {
            uint32_t aa = (uint32_t)(((arow_f + mt * 16) * SA_STR + asel) * 2);
            ldsm_x4(fah[0][mt][0], fah[0][mt][1], fah[0][mt][2], fah[0][mt][3], uAh + aa);
            ldsm_x4(fal[0][mt][0], fal[0][mt][1], fal[0][mt][2], fal[0][mt][3], uAl + aa);
        }

#pragma unroll
        for (int ks = 0; ks < 4; ks++) {
            int cur = ks & 1, nxt = cur ^ 1;
            if (ks < 3) {
                int ko = (ks + 1) * 16;
#pragma unroll
                for (int nt = 0; nt < 4; nt++) {
                    uint32_t ba = (uint32_t)(((brow + nt * 8) * SA_STR + ko + bsel) * 2);
                    ldsm_x2(fbh[nxt][nt][0], fbh[nxt][nt][1], uBh + ba);
                    ldsm_x2(fbl[nxt][nt][0], fbl[nxt][nt][1], uBl + ba);
                }
#pragma unroll
                for (int mt = 0; mt < 4; mt++) {
                    uint32_t aa = (uint32_t)(((arow_f + mt * 16) * SA_STR + ko + asel) * 2);
                    ldsm_x4(fah[nxt][mt][0], fah[nxt][mt][1], fah[nxt][mt][2], fah[nxt][mt][3],
                            uAh + aa);
                    ldsm_x4(fal[nxt][mt][0], fal[nxt][mt][1], fal[nxt][mt][2], fal[nxt][mt][3],
                            uAl + aa);
                }
            }
#pragma unroll
            for (int mt = 0; mt < 4; mt++) {
#pragma unroll
                for (int nt = 0; nt < 4; nt++) {
                    mma16816(acc[mt][nt], fah[cur][mt], fbh[cur][nt]);
                    mma16816(acc[mt][nt], fah[cur][mt], fbl[cur][nt]);
                    mma16816(acc[mt][nt], fal[cur][mt], fbh[cur][nt]);
                }
            }
        }
        __syncthreads();
    }

    // epilogue
    int erow = m0 + wm + (lane >> 2);
    int ecol0 = n0 + wn + (lane & 3) * 2;
#pragma unroll
    for (int mt = 0; mt < 4; mt++) {
        int row_a = erow + mt * 16;
        int row_b = row_a + 8;
#pragma unroll
        for (int nt = 0; nt < 4; nt++) {
            int cc = ecol0 + nt * 8;
            float b0 = bias[cc], b1 = bias[cc + 1];
            if (row_a < M) {
                float2 o = make_float2(acc[mt][nt][0] + b0, acc[mt][nt][1] + b1);
                *(float2*)(C + (size_t)row_a * Ncols + cc) = o;
            }
            if (row_b < M) {
                float2 o = make_float2(acc[mt][nt][2] + b0, acc[mt][nt][3] + b1);
                *(float2*)(C + (size_t)row_b * Ncols + cc) = o;
            }
        }
    }
}

// ---------------- kernel: parallel precompute (warp per output row) ----------------
#define PRE_WARPS 1689
__global__ __launch_bounds__(256) void k_pre(const float* __restrict__ dW,
                                             const float* __restrict__ db,
                                             const float* __restrict__ fW,
                                             const float* __restrict__ fb,
                                             const float* __restrict__ wW,
                                             const float* __restrict__ wb,
                                             const float* __restrict__ aW,
                                             const float* __restrict__ ab)
{
    int w = blockIdx.x * 8 + (threadIdx.x >> 5);
    int lane = threadIdx.x & 31;

    if (w < 128) {
        int i = w;
        float s1 = 0.f, s2 = 0.f;
#pragma unroll
        for (int t = 0; t < 8; t++) {
            int j = lane + t * 32;
            float u = fW[j] + fW[512 + j];
            float v = fW[256 + j] - fW[512 + j];
            float x = dW[i * H_DIM + j];
            s1 = fmaf(x, u, s1);
            s2 = fmaf(x, v, s2);
        }
        s1 = warp_sum(s1);
        s2 = warp_sum(s2);
        if (lane == 0) { g_du[i] = s1; g_dv[i] = s2; }
    } else if (w < 128 + 1536) {
        int t = w - 128;
        int r = t >> 9, rem = t & 511, hd = rem >> 7, i = rem & 127;
        const float* wr = wW + ((size_t)r * IN_F + i) * H_DIM + hd * HFEAT;
        const float* a1 = aW + r * 2 * HFEAT;
        const float* a2 = a1 + HFEAT;
        float p = 0.f, q = 0.f;
#pragma unroll
        for (int tt = 0; tt < 2; tt++) {
            int k = lane + tt * 32;
            float x = wr[k];
            p = fmaf(x, a1[k], p);
            q = fmaf(x, a2[k], q);
        }
        p = warp_sum(p);
        q = warp_sum(q);
        if (lane == 0) {
            g_PQ[r * (IN_F * 8) + i * 8 + hd]     = p;
            g_PQ[r * (IN_F * 8) + i * 8 + 4 + hd] = q;
        }
    } else if (w == 1664) {
        float cs = 0.f;
#pragma unroll
        for (int t = 0; t < 8; t++) {
            int j = lane + t * 32;
            float u = fW[j] + fW[512 + j];
            float v = fW[256 + j] - fW[512 + j];
            cs = fmaf(db[j], u + v, cs);
        }
        cs = warp_sum(cs);
        if (lane == 0) g_Cs = cs + fb[0];
    } else if (w < PRE_WARPS) {
        int t = w - 1665;
        int r = t >> 3, idx = t & 7;
        int hd = idx & 3;
        int isQ = idx >> 2;
        const float* wr = wb + r * H_DIM + hd * HFEAT;
        const float* av = aW + r * 2 * HFEAT + isQ * HFEAT;
        float acc = 0.f;
#pragma unroll
        for (int tt = 0; tt < 2; tt++) {
            int k = lane + tt * 32;
            acc = fmaf(wr[k], av[k], acc);
        }
        acc = warp_sum(acc);
        if (lane == 0) g_pqc[r * 8 + idx] = acc + (isQ ? ab[r] : 0.f);
    }
}

// ---------------- kernel: split h into bf16 hi/lo ----------------
__global__ void k_split_h(const float* __restrict__ h)
{
    int i = blockIdx.x * blockDim.x + threadIdx.x;
    if (i < N_NODES * IN_F) {
        __nv_bfloat16 hi, lo;
        split_bf16(h[i], hi, lo);
        g_hh[i] = hi;
        g_hl[i] = lo;
    }
}

// ---------------- kernel: transpose + split weights into bf16 hi/lo ----------------
__global__ void k_conv_w(const float* __restrict__ wW, const float* __restrict__ linW)
{
    int i = blockIdx.x * blockDim.x + threadIdx.x;
    if (i < RH * IN_F) {
        int j = i >> 7, k = i & 127;
        int r = j >> 8, cc = j & 255;
        __nv_bfloat16 hi, lo;
        split_bf16(wW[((size_t)r * IN_F + k) * H_DIM + cc], hi, lo);
        g_B1h[i] = hi;
        g_B1l[i] = lo;
    } else {
        int i2 = i - RH * IN_F;
        if (i2 < H_DIM * RH) {
            int cc = i2 / RH, k = i2 - cc * RH;
            __nv_bfloat16 hi, lo;
            split_bf16(linW[(size_t)k * H_DIM + cc], hi, lo);
            g_B2h[i2] = hi;
            g_B2l[i2] = lo;
        }
    }
}

// ---------------- kernel: per-node scalars (warp per node) ----------------
__global__ __launch_bounds__(128) void k_node_scalars(const float* __restrict__ h)
{
    int warp = threadIdx.x >> 5;
    int lane = threadIdx.x & 31;
    int node = blockIdx.x * 4 + warp;
    if (node >= N_NODES) return;

    float4 h4 = *(const float4*)(h + (size_t)node * IN_F + lane * 4);
    const float* hv = (const float*)&h4;

    float a = 0.f, b = 0.f;
    float pr[24];
#pragma unroll
    for (int j = 0; j < 24; j++) pr[j] = 0.f;

#pragma unroll
    for (int t = 0; t < 4; t++) {
        float x = hv[t];
        int idx = lane * 4 + t;
        a = fmaf(x, g_du[idx], a);
        b = fmaf(x, g_dv[idx], b);
#pragma unroll
        for (int r = 0; r < R_REL; r++) {
            const float4* pq4 = (const float4*)&g_PQ[r * (IN_F * 8) + idx * 8];
            float4 c0 = pq4[0], c1 = pq4[1];
            const float* c = (const float*)&c0;
            const float* d = (const float*)&c1;
#pragma unroll
            for (int j = 0; j < 4; j++) {
                pr[r * 8 + j]     = fmaf(x, c[j], pr[r * 8 + j]);
                pr[r * 8 + 4 + j] = fmaf(x, d[j], pr[r * 8 + 4 + j]);
            }
        }
    }
#pragma unroll
    for (int off = 16; off; off >>= 1) {
        a += __shfl_xor_sync(0xffffffffu, a, off);
        b += __shfl_xor_sync(0xffffffffu, b, off);
#pragma unroll
        for (int j = 0; j < 24; j++)
            pr[j] += __shfl_xor_sync(0xffffffffu, pr[j], off);
    }
    if (lane == 0) {
        g_sa[node] = a;
        g_sb[node] = b;
#pragma unroll
        for (int r = 0; r < R_REL; r++)
#pragma unroll
            for (int j = 0; j < 8; j++)
                g_pq[((size_t)r * N_NODES + node) * 8 + j] = pr[r * 8 + j] + g_pqc[r * 8 + j];
    }
}

// ---------------- CSR build ----------------
__global__ void k_zero()
{
    int i = blockIdx.x * blockDim.x + threadIdx.x;
    if (i < RN) g_cnt[i] = 0;
}

__global__ void k_hist(const int* __restrict__ dst)
{
    int i = blockIdx.x * blockDim.x + threadIdx.x;
    int r = blockIdx.y;
    if (i < E_EDGES)
        atomicAdd(&g_cnt[r * N_NODES + dst[(size_t)r * E_EDGES + i]], 1);
}

__global__ __launch_bounds__(256) void k_scan1()
{
    __shared__ int ws[8];
    int blk = blockIdx.x, tid = threadIdx.x;
    int base = blk * 1024 + tid * 4;
    int v[4];
#pragma unroll
    for (int j = 0; j < 4; j++) {
        int i = base + j;
        v[j] = (i < RN) ? g_cnt[i] : 0;
    }
    int s = v[0] + v[1] + v[2] + v[3];
    int lane = tid & 31, w = tid >> 5;
    int ps = s;
#pragma unroll
    for (int off = 1; off < 32; off <<= 1) {
        int t = __shfl_up_sync(0xffffffffu, ps, off);
        if (lane >= off) ps += t;
    }
    if (lane == 31) ws[w] = ps;
    __syncthreads();
    if (w == 0) {
        int t = (lane < 8) ? ws[lane] : 0;
#pragma unroll
        for (int off = 1; off < 8; off <<= 1) {
            int u = __shfl_up_sync(0xffffffffu, t, off);
            if (lane >= off) t += u;
        }
        if (lane < 8) ws[lane] = t;
    }
    __syncthreads();
    int excl = ps - s + (w ? ws[w - 1] : 0);
    int run = excl;
#pragma unroll
    for (int j = 0; j < 4; j++) {
        int i = base + j;
        if (i < RN) g_pre[i] = run;
        run += v[j];
    }
    if (tid == 255) g_bsum[blk] = ws[7];
}

__global__ __launch_bounds__(256) void k_scan2()
{
    __shared__ int sm[256];
    int tid = threadIdx.x;
    int v = (tid < NCHUNK) ? g_bsum[tid] : 0;
    sm[tid] = v;
    __syncthreads();
#pragma unroll
    for (int off = 1; off < 256; off <<= 1) {
        int t = (tid >= off) ? sm[tid - off] : 0;
        __syncthreads();
        sm[tid] += t;
        __syncthreads();
    }
    if (tid < NCHUNK) g_boff[tid] = sm[tid] - v;
}

__global__ __launch_bounds__(256) void k_scan3()
{
    int blk = blockIdx.x, tid = threadIdx.x;
    int add = g_boff[blk];
    int base = blk * 1024 + tid * 4;
#pragma unroll
    for (int j = 0; j < 4; j++) {
        int i = base + j;
        if (i < RN) {
            int o = g_pre[i] + add;
            g_off[i] = o;
            g_cur[i] = o;
        }
    }
    if (blk == 0 && tid == 0) g_off[RN] = RE;
}

// scatter: store the SOURCE NODE ID directly (kills one indirection in k_agg)
__global__ void k_scatter(const int* __restrict__ dst, const int* __restrict__ src)
{
    int i = blockIdx.x * blockDim.x + threadIdx.x;
    int r = blockIdx.y;
    if (i < E_EDGES) {
        size_t e = (size_t)r * E_EDGES + i;
        int pos = atomicAdd(&g_cur[r * N_NODES + dst[e]], 1);
        g_elist[pos] = src[e];
    }
}

// ---------------- aggregation: warp per (relation, node), single-pass softmax ----------------
__global__ __launch_bounds__(256) void k_agg()
{
    int widx = (blockIdx.x * blockDim.x + threadIdx.x) >> 5;
    int lane = threadIdx.x & 31;
    if (widx >= RN) return;
    int r = widx / N_NODES;
    int n = widx - r * N_NODES;
    int start = g_off[widx], end = g_off[widx + 1];
    size_t obase = (size_t)n * RH + r * H_DIM;
    uint2* oh = (uint2*)(g_aggh + obase);
    uint2* ol = (uint2*)(g_aggl + obase);

    if (start == end) {
#pragma unroll
        for (int j = 0; j < 2; j++) {
            oh[lane + 32 * j] = make_uint2(0u, 0u);
            ol[lane + 32 * j] = make_uint2(0u, 0u);
        }
        return;
    }

    float qv[4];
    {
        const float* qp = &g_pq[((size_t)r * N_NODES + n) * 8 + 4];
#pragma unroll
        for (int hh = 0; hh < 4; hh++) qv[hh] = qp[hh];
    }
    float b_n = g_sb[n] + g_Cs;
    const float* hwbase = g_hw + r * H_DIM;
    const float* pqR = g_pq + (size_t)r * N_NODES * 8;

    float den[4];
    float4 acc[2];
#pragma unroll
    for (int hh = 0; hh < 4; hh++) den[hh] = 0.f;
    acc[0] = make_float4(0.f, 0.f, 0.f, 0.f);
    acc[1] = make_float4(0.f, 0.f, 0.f, 0.f);

    int s_cur = g_elist[start];
    float4 pv_cur = *(const float4*)&pqR[(size_t)s_cur * 8];
    float sa_cur = g_sa[s_cur];

    for (int pos = start; pos < end; pos++) {
        int s = s_cur;
        float4 pv = pv_cur;
        float sav = sa_cur;
        if (pos + 1 < end) {
            s_cur = g_elist[pos + 1];
            pv_cur = *(const float4*)&pqR[(size_t)s_cur * 8];
            sa_cur = g_sa[s_cur];
        }
        float sc = sav + b_n;
        float sgn = (float)((sc > 0.f) - (sc < 0.f));
        float pvv[4] = {pv.x, pv.y, pv.z, pv.w};
        float w[4];
#pragma unroll
        for (int hh = 0; hh < 4; hh++) {
            float al = fmaf(sgn, pvv[hh], qv[hh]);
            al = (al > 0.f) ? al : 0.01f * al;
            float ev = __expf(al);
            den[hh] += ev;
            w[hh] = ev * sgn;
        }
        const float4* row4 = (const float4*)(hwbase + (size_t)s * RH);
#pragma unroll
        for (int j = 0; j < 2; j++) {
            float4 v = row4[lane + 32 * j];
            float wv = w[(lane >> 4) + 2 * j];
            acc[j].x = fmaf(wv, v.x, acc[j].x);
            acc[j].y = fmaf(wv, v.y, acc[j].y);
            acc[j].z = fmaf(wv, v.z, acc[j].z);
            acc[j].w = fmaf(wv, v.w, acc[j].w);
        }
    }
#pragma unroll
    for (int j = 0; j < 2; j++) {
        float inv = 1.f / den[(lane >> 4) + 2 * j];
        float v0 = acc[j].x * inv, v1 = acc[j].y * inv;
        float v2 = acc[j].z * inv, v3 = acc[j].w * inv;
        __nv_bfloat16 h0, l0, h1, l1, h2, l2, h3, l3;
        split_bf16(v0, h0, l0);
        split_bf16(v1, h1, l1);
        split_bf16(v2, h2, l2);
        split_bf16(v3, h3, l3);
        oh[lane + 32 * j] = make_uint2(pack_bf2(h0, h1), pack_bf2(h2, h3));
        ol[lane + 32 * j] = make_uint2(pack_bf2(l0, l1), pack_bf2(l2, l3));
    }
}

// ---------------- launch ----------------
extern "C" void kernel_launch(void* const* d_in, const int* in_sizes, int n_in,
                              void* d_out, int out_size)
{
    const float* h    = (const float*)d_in[0];
    const float* dW   = (const float*)d_in[1];
    const float* db   = (const float*)d_in[2];
    const float* fW   = (const float*)d_in[3];
    const float* fb   = (const float*)d_in[4];
    const float* wW   = (const float*)d_in[5];
    const float* wb   = (const float*)d_in[6];
    const float* aW   = (const float*)d_in[7];
    const float* ab   = (const float*)d_in[8];
    const float* linW = (const float*)d_in[9];
    const float* linb = (const float*)d_in[10];
    const int*   src  = (const int*)d_in[11];
    const int*   dst  = (const int*)d_in[12];
    float* out = (float*)d_out;

    float* p_hw = nullptr;
    __nv_bfloat16 *p_hh, *p_hl, *p_aggh, *p_aggl, *p_B1h, *p_B1l, *p_B2h, *p_B2l;
    cudaGetSymbolAddress((void**)&p_hw, g_hw);
    cudaGetSymbolAddress((void**)&p_hh, g_hh);
    cudaGetSymbolAddress((void**)&p_hl, g_hl);
    cudaGetSymbolAddress((void**)&p_aggh, g_aggh);
    cudaGetSymbolAddress((void**)&p_aggl, g_aggl);
    cudaGetSymbolAddress((void**)&p_B1h, g_B1h);
    cudaGetSymbolAddress((void**)&p_B1l, g_B1l);
    cudaGetSymbolAddress((void**)&p_B2h, g_B2h);
    cudaGetSymbolAddress((void**)&p_B2l, g_B2l);

    cudaFuncSetAttribute(k_gemm_mma, cudaFuncAttributeMaxDynamicSharedMemorySize, MM_SMEM);

    int nwelem = RH * IN_F + H_DIM * RH;
    k_pre<<<(PRE_WARPS + 7) / 8, 256>>>(dW, db, fW, fb, wW, wb, aW, ab);  // 1
    k_conv_w<<<(nwelem + 255) / 256, 256>>>(wW, linW);                   // 2
    k_split_h<<<(N_NODES * IN_F + 255) / 256, 256>>>(h);                 // 3
    k_gemm_mma<<<dim3(RH / 128, (N_NODES + 127) / 128), 256, MM_SMEM>>>(
        p_hh, p_hl, p_B1h, p_B1l, wb, p_hw, N_NODES, RH, IN_F);          // 4 (GEMM1 @ capture slot)
    k_zero<<<(RN + 255) / 256, 256>>>();                                 // 5
    k_node_scalars<<<N_NODES / 4, 128>>>(h);                             // 6
    k_hist<<<dim3((E_EDGES + 255) / 256, R_REL), 256>>>(dst);            // 7
    k_scan1<<<NCHUNK, 256>>>();                                          // 8a
    k_scan2<<<1, 256>>>();                                               // 8b
    k_scan3<<<NCHUNK, 256>>>();                                          // 8c
    k_scatter<<<dim3((E_EDGES + 255) / 256, R_REL), 256>>>(dst, src);    // 9
    k_agg<<<RN / 8, 256>>>();                                            // 10
    k_gemm_mma<<<dim3(H_DIM / 128, (N_NODES + 127) / 128), 256, MM_SMEM>>>(
        p_aggh, p_aggl, p_B2h, p_B2l, linb, out, N_NODES, H_DIM, RH);    // 11 (GEMM2)
}